// round 13
// baseline (speedup 1.0000x reference)
#include <cuda_runtime.h>
#include <cuda_bf16.h>
#include <math.h>
#include <stdint.h>

typedef unsigned long long u64;

#define Bn 128
#define Tn 256
#define Dn 512
#define Hn 256
#define G3 768    // 3*H
#define H2 512    // 2*H
#define KE 1536   // extended K (B operand; A reuses hi chunk)
#define KA 1024   // A operand stored K: [hi | lo]
#define XG_STRIDE (Bn*Tn*G3)   // 25,165,824

// scan smem layout (floats): weights [3][256][64] | h [2][256][8] | partials
#define SCAN_W_FLOATS (3*256*64)            // 49152
#define SCAN_H_FLOATS (2*256*8)             // 4096
#define SCAN_P_U64    (128*6)               // 768
#define SCAN_SMEM_BYTES ((SCAN_W_FLOATS + SCAN_H_FLOATS)*4 + SCAN_P_U64*8)  // 219136

// ---------------- device scratch ----------------
__device__ float g_xg[2*Bn*Tn*G3];         // [dir][b][t][3H] input gates (+b_ih)
__device__ __nv_bfloat16 g_aext[(size_t)Bn*Tn*KA];  // [bt][KA]  split feats (hi|lo)
__device__ __nv_bfloat16 g_wext[2*G3*KE];           // [gate2dir][KE] split w_ih (hi|hi|lo)
__device__ float g_wsc[2*4*SCAN_W_FLOATS]; // [dir][rank][3][256][64] scan weights
__device__ float g_out[Bn*Tn*H2];          // [b][t][2H]
__device__ float g_scores[Bn*Tn];          // [b][t]
__device__ float g_w1t[H2*64];             // [h][o] w1 transposed

// ---------------- f32x2 helpers ----------------
__device__ __forceinline__ u64 fma2(u64 a, u64 b, u64 c) {
    u64 d;
    asm("fma.rn.f32x2 %0, %1, %2, %3;" : "=l"(d) : "l"(a), "l"(b), "l"(c));
    return d;
}
__device__ __forceinline__ u64 add2(u64 a, u64 b) {
    u64 d;
    asm("add.rn.f32x2 %0, %1, %2;" : "=l"(d) : "l"(a), "l"(b));
    return d;
}
__device__ __forceinline__ u64 pack2(float x, float y) {
    u64 d;
    asm("mov.b64 %0, {%1, %2};" : "=l"(d) : "f"(x), "f"(y));
    return d;
}
__device__ __forceinline__ float2 unpack2(u64 v) {
    float2 r;
    asm("mov.b64 {%0, %1}, %2;" : "=f"(r.x), "=f"(r.y) : "l"(v));
    return r;
}
__device__ __forceinline__ float sigm(float x) { return 1.f / (1.f + expf(-x)); }

__device__ __forceinline__ void dsmem_st_u64(uint32_t laddr, int trank, u64 v) {
    asm volatile(
        "{\n\t.reg .b32 ra;\n\t"
        "mapa.shared::cluster.u32 ra, %0, %1;\n\t"
        "st.shared::cluster.b64 [ra], %2;\n\t}"
        :: "r"(laddr), "r"(trank), "l"(v) : "memory");
}
#define CLUSTER_SYNC() do { \
    asm volatile("barrier.cluster.arrive.aligned;" ::: "memory"); \
    asm volatile("barrier.cluster.wait.aligned;"   ::: "memory"); } while (0)

// ---------------- mma.sync helpers (HMMA, baseline sm_80+ PTX) ----------------
__device__ __forceinline__ void ldsm4(uint32_t* r, uint32_t addr) {
    asm volatile("ldmatrix.sync.aligned.m8n8.x4.shared.b16 {%0,%1,%2,%3}, [%4];"
        : "=r"(r[0]), "=r"(r[1]), "=r"(r[2]), "=r"(r[3]) : "r"(addr));
}
__device__ __forceinline__ void mma16816(float* d, const uint32_t* a,
                                         uint32_t b0, uint32_t b1) {
    asm volatile(
        "mma.sync.aligned.m16n8k16.row.col.f32.bf16.bf16.f32 "
        "{%0,%1,%2,%3}, {%4,%5,%6,%7}, {%8,%9}, {%0,%1,%2,%3};"
        : "+f"(d[0]), "+f"(d[1]), "+f"(d[2]), "+f"(d[3])
        : "r"(a[0]), "r"(a[1]), "r"(a[2]), "r"(a[3]), "r"(b0), "r"(b1));
}

// ---------------- prep: scan weight relayout + w1t ----------------
__global__ void prep_kernel(const float* __restrict__ w_hh_f,
                            const float* __restrict__ w_hh_b,
                            const float* __restrict__ w1) {
    int idx = blockIdx.x * blockDim.x + threadIdx.x;
    if (idx < 2*4*SCAN_W_FLOATS) {
        int i = idx & 63;
        int t1 = idx >> 6;
        int k = t1 & 255;
        int t2 = t1 >> 8;
        int g = t2 % 3;
        int t3 = t2 / 3;
        int r = t3 & 3;
        int d = t3 >> 2;
        int row = g * 256 + r * 64 + i;
        const float* src = d ? w_hh_b : w_hh_f;
        g_wsc[idx] = src[row * 256 + k];
    }
    if (idx < 64 * H2) {
        int o = idx / H2;
        int h = idx % H2;
        g_w1t[h * 64 + o] = w1[idx];
    }
}

// ---------------- prep: bf16 hi/lo split ----------------
// A stored [hi | lo] (KA=1024); GEMM reuses hi for the 3rd term.
// W_ext[j] = [hi | hi | lo] (KE=1536).
__global__ void prep_split(const float* __restrict__ feats,
                           const float* __restrict__ w_ih_f,
                           const float* __restrict__ w_ih_b) {
    int idx = blockIdx.x * blockDim.x + threadIdx.x;
    if (idx < Bn*Tn*Dn) {
        int row = idx >> 9, k = idx & 511;
        float a = feats[idx];
        __nv_bfloat16 hi = __float2bfloat16(a);
        __nv_bfloat16 lo = __float2bfloat16(a - __bfloat162float(hi));
        __nv_bfloat16* dst = g_aext + (size_t)row * KA;
        dst[k] = hi; dst[512 + k] = lo;
    } else {
        int j2 = idx - Bn*Tn*Dn;
        if (j2 < 2*G3*Dn) {
            int row = j2 >> 9, k = j2 & 511;
            float w = (row < G3) ? w_ih_f[row * 512 + k]
                                 : w_ih_b[(row - G3) * 512 + k];
            __nv_bfloat16 hi = __float2bfloat16(w);
            __nv_bfloat16 lo = __float2bfloat16(w - __bfloat162float(hi));
            __nv_bfloat16* dst = g_wext + (size_t)row * KE;
            dst[k] = hi; dst[512 + k] = hi; dst[1024 + k] = lo;
        }
    }
}

// ---------------- input-gate GEMM on HMMA (mma.sync bf16) ----------------
// C[32768,1536] = A_ext @ W_ext^T + bias.  BM=128 BN=128 BK=32,
// 8 warps (4m x 2n), warp tile 32x64, fp32 accum.
// Grid (n=12, m=256): adjacent CTAs share the A m-tile via L2.
__global__ void __launch_bounds__(256) xg_gemm_mma(const float* __restrict__ bfv,
                                                   const float* __restrict__ bbv) {
    __shared__ __align__(16) __nv_bfloat16 As[128][40];  // 40 = 32 + 8 pad
    __shared__ __align__(16) __nv_bfloat16 Bs[128][40];

    const int tid  = threadIdx.x;
    const int lane = tid & 31;
    const int wid  = tid >> 5;
    const int wm   = wid >> 1;     // 0..3
    const int wn   = wid & 1;      // 0..1
    const int col0 = blockIdx.x * 128;   // N base (12 tiles)
    const int row0 = blockIdx.y * 128;   // M base (256 tiles)

    const __nv_bfloat16* __restrict__ Abase = g_aext + (size_t)row0 * KA;
    const __nv_bfloat16* __restrict__ Bbase = g_wext + (size_t)col0 * KE;

    uint32_t sA = (uint32_t)__cvta_generic_to_shared(&As[0][0]);
    uint32_t sB = (uint32_t)__cvta_generic_to_shared(&Bs[0][0]);

    float d[2][8][4];
#pragma unroll
    for (int mt = 0; mt < 2; mt++)
#pragma unroll
        for (int nt = 0; nt < 8; nt++)
#pragma unroll
            for (int e = 0; e < 4; e++) d[mt][nt][e] = 0.f;

    // prefetch assignment: thread t -> rows (t>>2, t>>2 + 64), 16B chunk (t&3)
    const int pr = tid >> 2;
    const int pq = (tid & 3) * 8;    // bf16 offset
    uint4 ra[2], rb[2];
#pragma unroll
    for (int s = 0; s < 2; s++) {
        ra[s] = *(const uint4*)(Abase + (size_t)(pr + s*64) * KA + pq);
        rb[s] = *(const uint4*)(Bbase + (size_t)(pr + s*64) * KE + pq);
    }

    // ldmatrix lane addresses
    const int a_r = (lane & 15);
    const int a_c = (lane >> 4) * 8;
    const int b_r = (lane & 7) + ((lane >> 4) << 3);
    const int b_c = ((lane >> 3) & 1) * 8;

    for (int c = 0; c < 48; c++) {
#pragma unroll
        for (int s = 0; s < 2; s++) {
            *(uint4*)&As[pr + s*64][pq] = ra[s];
            *(uint4*)&Bs[pr + s*64][pq] = rb[s];
        }
        __syncthreads();
        if (c < 47) {
            // A chunk index wraps: chunks 32..47 re-read the hi part (0..15)
            int cn = c + 1;
            int an = (cn < 32) ? cn : (cn - 32);
            const __nv_bfloat16* ap = Abase + (size_t)an * 32 + pq;
            const __nv_bfloat16* bp = Bbase + (size_t)cn * 32 + pq;
#pragma unroll
            for (int s = 0; s < 2; s++) {
                ra[s] = *(const uint4*)(ap + (size_t)(pr + s*64) * KA);
                rb[s] = *(const uint4*)(bp + (size_t)(pr + s*64) * KE);
            }
        }
#pragma unroll
        for (int ks = 0; ks < 2; ks++) {
            uint32_t af[2][4];
#pragma unroll
            for (int mt = 0; mt < 2; mt++) {
                int row = wm*32 + mt*16 + a_r;
                int col = ks*16 + a_c;
                ldsm4(af[mt], sA + (uint32_t)(row * 40 + col) * 2);
            }
#pragma unroll
            for (int p = 0; p < 4; p++) {
                uint32_t bfr[4];
                int row = wn*64 + p*16 + b_r;
                int col = ks*16 + b_c;
                ldsm4(bfr, sB + (uint32_t)(row * 40 + col) * 2);
#pragma unroll
                for (int mt = 0; mt < 2; mt++) {
                    mma16816(d[mt][2*p],     af[mt], bfr[0], bfr[1]);
                    mma16816(d[mt][2*p + 1], af[mt], bfr[2], bfr[3]);
                }
            }
        }
        __syncthreads();
    }

    // epilogue: add bias, store fp32 to g_xg
    const int dir = (col0 >= G3) ? 1 : 0;
    const int j0  = col0 - dir * G3;
    const float* __restrict__ bias = dir ? bbv : bfv;
    float* __restrict__ outb = g_xg + (size_t)dir * XG_STRIDE;
#pragma unroll
    for (int nt = 0; nt < 8; nt++) {
        const int gn = j0 + wn*64 + nt*8 + (lane & 3) * 2;
        const float bx = bias[gn], by = bias[gn + 1];
#pragma unroll
        for (int mt = 0; mt < 2; mt++) {
            const int gm = row0 + wm*32 + mt*16 + (lane >> 2);
            float2 lo = make_float2(d[mt][nt][0] + bx, d[mt][nt][1] + by);
            float2 hi = make_float2(d[mt][nt][2] + bx, d[mt][nt][3] + by);
            *(float2*)(outb + (size_t)gm * G3 + gn)       = lo;
            *(float2*)(outb + (size_t)(gm + 8) * G3 + gn) = hi;
        }
    }
}

// ---------------- recurrent scan: cluster-4, smem-resident weights ----------------
__global__ void __launch_bounds__(256, 1) __cluster_dims__(4, 1, 1)
scan_kernel(const float* __restrict__ b_hh_f,
            const float* __restrict__ b_hh_b,
            const int*   __restrict__ lengths) {
    extern __shared__ __align__(16) float smem[];
    float* w_s = smem;                                   // [3][256][64]
    float* h_s = smem + SCAN_W_FLOATS;                   // [2][256][8]
    u64*  part = (u64*)(smem + SCAN_W_FLOATS + SCAN_H_FLOATS); // [128][6]

    const int myrank = blockIdx.x & 3;
    const int cid    = blockIdx.x >> 2;
    const int dir    = cid >> 4;
    const int bg     = cid & 15;
    const int b0     = bg * 8;

    const int tid = threadIdx.x;
    const int i   = tid & 63;
    const int q   = (tid >> 6) & 1;
    const int kh  = tid >> 7;
    const int gu  = myrank * 64 + i;

    {
        const float4* src = (const float4*)(g_wsc + (size_t)(dir * 4 + myrank) * SCAN_W_FLOATS);
        float4* dst = (float4*)w_s;
#pragma unroll
        for (int f = tid; f < SCAN_W_FLOATS / 4; f += 256) dst[f] = src[f];
        for (int f = tid; f < SCAN_H_FLOATS; f += 256) h_s[f] = 0.f;
    }
    const float* bh = dir ? b_hh_b : b_hh_f;
    const float bhr = bh[gu], bhz = bh[Hn + gu], bhn = bh[2 * Hn + gu];
    int lens[4];
#pragma unroll
    for (int j = 0; j < 4; j++) lens[j] = lengths[b0 + 4 * q + j];

    __syncthreads();
    CLUSTER_SYNC();

    const float* __restrict__ XG = g_xg + (size_t)dir * XG_STRIDE;
    const u64 Z = pack2(0.f, 0.f);

    for (int t = 0; t < Tn; t++) {
        const int buf = t & 1, nb = 1 - buf;
        u64 ar0 = Z, ar1 = Z, az0 = Z, az1 = Z, an0 = Z, an1 = Z;

        const float* hb = h_s + buf * 2048 + q * 4 + kh * 128 * 8;
        const float* wp = w_s + kh * 128 * 64 + i;
#pragma unroll 4
        for (int k0 = 0; k0 < 128; k0++) {
            float wr = wp[0];
            float wz = wp[16384];
            float wn = wp[32768];
            ulonglong2 hv = *(const ulonglong2*)(hb + k0 * 8);
            u64 pr = pack2(wr, wr), pz = pack2(wz, wz), pn = pack2(wn, wn);
            ar0 = fma2(pr, hv.x, ar0); ar1 = fma2(pr, hv.y, ar1);
            az0 = fma2(pz, hv.x, az0); az1 = fma2(pz, hv.y, az1);
            an0 = fma2(pn, hv.x, an0); an1 = fma2(pn, hv.y, an1);
            wp += 64;
        }

        if (kh) {
            u64* pp = &part[(q * 64 + i) * 6];
            pp[0] = ar0; pp[1] = ar1; pp[2] = az0;
            pp[3] = az1; pp[4] = an0; pp[5] = an1;
        }
        __syncthreads();

        if (!kh) {
            const u64* pp = &part[(q * 64 + i) * 6];
            ar0 = add2(ar0, pp[0]); ar1 = add2(ar1, pp[1]);
            az0 = add2(az0, pp[2]); az1 = add2(az1, pp[3]);
            an0 = add2(an0, pp[4]); an1 = add2(an1, pp[5]);

            const float* hold = h_s + buf * 2048 + gu * 8 + q * 4;
            float ho[4] = {hold[0], hold[1], hold[2], hold[3]};
            float2 rA = unpack2(ar0), rB = unpack2(ar1);
            float2 zA = unpack2(az0), zB = unpack2(az1);
            float2 nA = unpack2(an0), nB = unpack2(an1);
            float arv[4] = {rA.x, rA.y, rB.x, rB.y};
            float azv[4] = {zA.x, zA.y, zB.x, zB.y};
            float anv[4] = {nA.x, nA.y, nB.x, nB.y};

            float hn4[4];
#pragma unroll
            for (int j = 0; j < 4; j++) {
                int b = 4 * q + j;
                int L = lens[j];
                int tsrc = dir ? ((t < L) ? (L - 1 - t) : t) : t;
                const float* xg = XG + ((size_t)(b0 + b) * Tn + tsrc) * G3;
                float r = sigm(xg[gu]           + arv[j] + bhr);
                float z = sigm(xg[Hn + gu]      + azv[j] + bhz);
                float n = tanhf(xg[2 * Hn + gu] + r * (anv[j] + bhn));
                float hq = (1.f - z) * n + z * ho[j];
                bool  m  = (t < L);
                int tout = dir ? tsrc : t;
                g_out[((size_t)(b0 + b) * Tn + tout) * H2 + dir * Hn + gu] = m ? hq : 0.f;
                hn4[j] = m ? hq : ho[j];
            }

            u64 v0 = pack2(hn4[0], hn4[1]);
            u64 v1 = pack2(hn4[2], hn4[3]);
            float* hdst = h_s + nb * 2048 + gu * 8 + q * 4;
            *(u64*)hdst       = v0;
            *(u64*)(hdst + 2) = v1;
            uint32_t laddr = (uint32_t)__cvta_generic_to_shared(hdst);
#pragma unroll
            for (int r2 = 0; r2 < 4; r2++) {
                if (r2 != myrank) {
                    dsmem_st_u64(laddr,     r2, v0);
                    dsmem_st_u64(laddr + 8, r2, v1);
                }
            }
        }
        CLUSTER_SYNC();
    }
}

// ---------------- score MLP (8 rows per block) ----------------
__global__ void __launch_bounds__(256) mlp_kernel(const float* __restrict__ b1,
                                                  const float* __restrict__ w2,
                                                  const float* __restrict__ b2) {
    const int bt0 = blockIdx.x * 8;
    const int tid = threadIdx.x;
    const int k2 = tid & 31;
    const int rg = tid >> 5;          // 0..7 -> row rg
    __shared__ __align__(16) float srow[8][512];

#pragma unroll
    for (int f = tid; f < 1024; f += 256) {
        int row = f >> 7, h4 = f & 127;
        ((float4*)srow[row])[h4] =
            *(const float4*)(g_out + (size_t)(bt0 + row) * H2 + 4 * h4);
    }
    __syncthreads();

    const u64 Z = pack2(0.f, 0.f);
    u64 acc0 = Z, acc1 = Z;           // two h-halves for ILP
    const float* __restrict__ w = g_w1t + 2 * k2;
#pragma unroll 4
    for (int h = 0; h < 256; h++) {
        u64 wv0 = *(const u64*)(w + h * 64);
        u64 wv1 = *(const u64*)(w + (h + 256) * 64);
        float s0 = srow[rg][h];
        float s1 = srow[rg][h + 256];
        acc0 = fma2(pack2(s0, s0), wv0, acc0);
        acc1 = fma2(pack2(s1, s1), wv1, acc1);
    }
    u64 acc = add2(acc0, acc1);
    float2 a0 = unpack2(acc);
    float b1a = b1[2 * k2], b1b = b1[2 * k2 + 1];
    float w2a = w2[2 * k2], w2b = w2[2 * k2 + 1];
    float p0 = fmaxf(a0.x + b1a, 0.f) * w2a + fmaxf(a0.y + b1b, 0.f) * w2b;
#pragma unroll
    for (int off = 16; off > 0; off >>= 1)
        p0 += __shfl_down_sync(0xffffffffu, p0, off);
    if (k2 == 0) g_scores[bt0 + rg] = p0 + b2[0];
}

// ---------------- softmax + top-3 attention + heads ----------------
__global__ void final_kernel(const int*   __restrict__ lengths,
                             const float* __restrict__ temp_p,
                             const float* __restrict__ w_tens,
                             const float* __restrict__ b_tens,
                             const float* __restrict__ w_ones,
                             const float* __restrict__ b_ones,
                             float* __restrict__ out) {
    const int bb  = blockIdx.x;
    const int tid = threadIdx.x;
    __shared__ float sp[Tn];
    __shared__ float sred[Tn];
    __shared__ __align__(16) float sfeat[H2];
    __shared__ int   s_topi[3];
    __shared__ float s_topw[3];
    __shared__ int   s_fallback;

    const int len = lengths[bb];
    float temp = fminf(fmaxf(temp_p[0], 0.001f), 10.f);

    float sc = (tid < len) ? (g_scores[bb * Tn + tid] / temp) : -INFINITY;

    sred[tid] = sc; __syncthreads();
    for (int s = 128; s > 0; s >>= 1) {
        if (tid < s) sred[tid] = fmaxf(sred[tid], sred[tid + s]);
        __syncthreads();
    }
    float mx = sred[0]; __syncthreads();

    float e = (tid < len) ? expf(sc - mx) : 0.f;
    sred[tid] = e; __syncthreads();
    for (int s = 128; s > 0; s >>= 1) {
        if (tid < s) sred[tid] += sred[tid + s];
        __syncthreads();
    }
    float denom = sred[0];
    sp[tid] = e / denom;
    __syncthreads();

    if (tid == 0) {
        int k_act = (len < 3) ? len : 3;
        int i0 = -1, i1 = -1, i2 = -1;
        int pi[3]; float pv[3];
        for (int r = 0; r < 3; r++) {
            float best = -1.f; int bi = 0;
            for (int t2 = 0; t2 < Tn; t2++) {
                if (t2 == i0 || t2 == i1 || t2 == i2) continue;
                float v = sp[t2];
                if (v > best) { best = v; bi = t2; }
            }
            pi[r] = bi; pv[r] = best;
            if (r == 0) i0 = bi; else if (r == 1) i1 = bi; else i2 = bi;
        }
        float vsum = 0.f;
        for (int r = 0; r < 3; r++) if (r < k_act) vsum += pv[r];
        if (vsum > 1e-8f) {
            s_fallback = 0;
            float dv = fmaxf(vsum, 1e-8f);
            for (int r = 0; r < 3; r++) {
                s_topi[r] = pi[r];
                s_topw[r] = (r < k_act) ? (pv[r] / dv) : 0.f;
            }
        } else {
            s_fallback = 1;
        }
    }
    __syncthreads();

    for (int h = tid; h < H2; h += 256) {
        float acc = 0.f;
        if (!s_fallback) {
#pragma unroll
            for (int r = 0; r < 3; r++) {
                float w = s_topw[r];
                if (w != 0.f)
                    acc += w * g_out[((size_t)(bb * Tn + s_topi[r])) * H2 + h];
            }
        } else {
            for (int t2 = 0; t2 < len; t2++)
                acc += g_out[((size_t)(bb * Tn + t2)) * H2 + h];
            acc /= ((float)len + 1e-8f);
        }
        sfeat[h] = acc;
    }
    __syncthreads();

    if (tid < 21) {
        const float* wrow; float bias;
        if (tid < 11) { wrow = w_tens + (size_t)tid * H2;        bias = b_tens[tid]; }
        else          { wrow = w_ones + (size_t)(tid - 11) * H2; bias = b_ones[tid - 11]; }
        float acc = bias;
#pragma unroll 8
        for (int h = 0; h < H2; h++) acc += sfeat[h] * wrow[h];
        if (tid < 11) out[bb * 11 + tid] = acc;
        else          out[Bn * 11 + bb * 10 + (tid - 11)] = acc;
    }
}

// ---------------- launch ----------------
extern "C" void kernel_launch(void* const* d_in, const int* in_sizes, int n_in,
                              void* d_out, int out_size) {
    const float* feats   = (const float*)d_in[0];
    const int*   lengths = (const int*)  d_in[1];
    const float* temp    = (const float*)d_in[2];
    const float* w_ih_f  = (const float*)d_in[3];
    const float* w_hh_f  = (const float*)d_in[4];
    const float* b_ih_f  = (const float*)d_in[5];
    const float* b_hh_f  = (const float*)d_in[6];
    const float* w_ih_b  = (const float*)d_in[7];
    const float* w_hh_b  = (const float*)d_in[8];
    const float* b_ih_b  = (const float*)d_in[9];
    const float* b_hh_b  = (const float*)d_in[10];
    const float* w1      = (const float*)d_in[11];
    const float* b1      = (const float*)d_in[12];
    const float* w2      = (const float*)d_in[13];
    const float* b2      = (const float*)d_in[14];
    const float* w_tens  = (const float*)d_in[15];
    const float* b_tens  = (const float*)d_in[16];
    const float* w_ones  = (const float*)d_in[17];
    const float* b_ones  = (const float*)d_in[18];
    float* out = (float*)d_out;

    cudaFuncSetAttribute(scan_kernel,
        cudaFuncAttributeMaxDynamicSharedMemorySize, SCAN_SMEM_BYTES);

    // slot 0
    prep_kernel<<<1536, 256>>>(w_hh_f, w_hh_b, w1);
    // slot 1
    {
        int total = Bn*Tn*Dn + 2*G3*Dn;
        prep_split<<<(total + 255) / 256, 256>>>(feats, w_ih_f, w_ih_b);
    }
    // slot 2
    {
        dim3 g((2 * G3) / 128, Bn * Tn / 128);   // (12, 256): A-tile L2 reuse
        xg_gemm_mma<<<g, 256>>>(b_ih_f, b_ih_b);
    }
    // slot 3 (profiler lands here -> scan gets measured this round)
    scan_kernel<<<128, 256, SCAN_SMEM_BYTES>>>(b_hh_f, b_hh_b, lengths);
    // slot 4
    mlp_kernel<<<Bn * Tn / 8, 256>>>(b1, w2, b2);
    // slot 5
    final_kernel<<<Bn, 256>>>(lengths, temp, w_tens, b_tens, w_ones, b_ones, out);
}

// round 15
// speedup vs baseline: 1.7229x; 1.7229x over previous
#include <cuda_runtime.h>
#include <cuda_bf16.h>
#include <math.h>
#include <stdint.h>

typedef unsigned long long u64;

#define Bn 128
#define Tn 256
#define Dn 512
#define Hn 256
#define G3 768    // 3*H
#define H2 512    // 2*H
#define KE 1536   // extended K (B operand; A reuses hi chunk)
#define KA 1024   // A operand stored K: [hi | lo]
#define XG_STRIDE (Bn*Tn*G3)   // 25,165,824

// scan smem layout (floats): weights [3][256][64] | h [2][256][8] | partials
#define SCAN_W_FLOATS (3*256*64)            // 49152
#define SCAN_H_FLOATS (2*256*8)             // 4096
#define SCAN_P_U64    (128*6)               // 768
#define SCAN_SMEM_BYTES ((SCAN_W_FLOATS + SCAN_H_FLOATS)*4 + SCAN_P_U64*8)  // 219136

// ---------------- device scratch ----------------
__device__ float g_xg[2*Bn*Tn*G3];         // [dir][b][t][3H] input gates (+b_ih)
__device__ __nv_bfloat16 g_aext[(size_t)Bn*Tn*KA];  // [bt][KA]  split feats (hi|lo)
__device__ __nv_bfloat16 g_wext[2*G3*KE];           // [gate2dir][KE] split w_ih (hi|hi|lo)
__device__ float g_wsc[2*4*SCAN_W_FLOATS]; // [dir][rank][3][256][64] scan weights
__device__ float g_out[Bn*Tn*H2];          // [b][t][2H]
__device__ float g_scores[Bn*Tn];          // [b][t]
__device__ float g_w1t[H2*64];             // [h][o] w1 transposed

// ---------------- f32x2 helpers ----------------
__device__ __forceinline__ u64 fma2(u64 a, u64 b, u64 c) {
    u64 d;
    asm("fma.rn.f32x2 %0, %1, %2, %3;" : "=l"(d) : "l"(a), "l"(b), "l"(c));
    return d;
}
__device__ __forceinline__ u64 add2(u64 a, u64 b) {
    u64 d;
    asm("add.rn.f32x2 %0, %1, %2;" : "=l"(d) : "l"(a), "l"(b));
    return d;
}
__device__ __forceinline__ u64 pack2(float x, float y) {
    u64 d;
    asm("mov.b64 %0, {%1, %2};" : "=l"(d) : "f"(x), "f"(y));
    return d;
}
__device__ __forceinline__ float2 unpack2(u64 v) {
    float2 r;
    asm("mov.b64 {%0, %1}, %2;" : "=f"(r.x), "=f"(r.y) : "l"(v));
    return r;
}
__device__ __forceinline__ float sigm(float x) { return 1.f / (1.f + expf(-x)); }

__device__ __forceinline__ void dsmem_st_u64(uint32_t laddr, int trank, u64 v) {
    asm volatile(
        "{\n\t.reg .b32 ra;\n\t"
        "mapa.shared::cluster.u32 ra, %0, %1;\n\t"
        "st.shared::cluster.b64 [ra], %2;\n\t}"
        :: "r"(laddr), "r"(trank), "l"(v) : "memory");
}
#define CLUSTER_SYNC() do { \
    asm volatile("barrier.cluster.arrive.aligned;" ::: "memory"); \
    asm volatile("barrier.cluster.wait.aligned;"   ::: "memory"); } while (0)
#define CLUSTER_ARRIVE() asm volatile("barrier.cluster.arrive.aligned;" ::: "memory")
#define CLUSTER_WAIT()   asm volatile("barrier.cluster.wait.aligned;"   ::: "memory")

// ---------------- mma.sync helpers (HMMA, baseline sm_80+ PTX) ----------------
__device__ __forceinline__ void ldsm4(uint32_t* r, uint32_t addr) {
    asm volatile("ldmatrix.sync.aligned.m8n8.x4.shared.b16 {%0,%1,%2,%3}, [%4];"
        : "=r"(r[0]), "=r"(r[1]), "=r"(r[2]), "=r"(r[3]) : "r"(addr));
}
__device__ __forceinline__ void mma16816(float* d, const uint32_t* a,
                                         uint32_t b0, uint32_t b1) {
    asm volatile(
        "mma.sync.aligned.m16n8k16.row.col.f32.bf16.bf16.f32 "
        "{%0,%1,%2,%3}, {%4,%5,%6,%7}, {%8,%9}, {%0,%1,%2,%3};"
        : "+f"(d[0]), "+f"(d[1]), "+f"(d[2]), "+f"(d[3])
        : "r"(a[0]), "r"(a[1]), "r"(a[2]), "r"(a[3]), "r"(b0), "r"(b1));
}
__device__ __forceinline__ void cp_async16(uint32_t smem_dst, const void* gmem_src) {
    asm volatile("cp.async.cg.shared.global [%0], [%1], 16;"
        :: "r"(smem_dst), "l"(gmem_src) : "memory");
}
#define CP_COMMIT()  asm volatile("cp.async.commit_group;" ::: "memory")
#define CP_WAIT(n)   asm volatile("cp.async.wait_group %0;" :: "n"(n) : "memory")

// ---------------- dummy (profiler slot positioning) ----------------
__global__ void dummy_kernel() {}

// ---------------- prep: scan weight relayout + w1t ----------------
__global__ void prep_kernel(const float* __restrict__ w_hh_f,
                            const float* __restrict__ w_hh_b,
                            const float* __restrict__ w1) {
    int idx = blockIdx.x * blockDim.x + threadIdx.x;
    if (idx < 2*4*SCAN_W_FLOATS) {
        int i = idx & 63;
        int t1 = idx >> 6;
        int k = t1 & 255;
        int t2 = t1 >> 8;
        int g = t2 % 3;
        int t3 = t2 / 3;
        int r = t3 & 3;
        int d = t3 >> 2;
        int row = g * 256 + r * 64 + i;
        const float* src = d ? w_hh_b : w_hh_f;
        g_wsc[idx] = src[row * 256 + k];
    }
    if (idx < 64 * H2) {
        int o = idx / H2;
        int h = idx % H2;
        g_w1t[h * 64 + o] = w1[idx];
    }
}

// ---------------- prep: bf16 hi/lo split ----------------
__global__ void prep_split(const float* __restrict__ feats,
                           const float* __restrict__ w_ih_f,
                           const float* __restrict__ w_ih_b) {
    int idx = blockIdx.x * blockDim.x + threadIdx.x;
    if (idx < Bn*Tn*Dn) {
        int row = idx >> 9, k = idx & 511;
        float a = feats[idx];
        __nv_bfloat16 hi = __float2bfloat16(a);
        __nv_bfloat16 lo = __float2bfloat16(a - __bfloat162float(hi));
        __nv_bfloat16* dst = g_aext + (size_t)row * KA;
        dst[k] = hi; dst[512 + k] = lo;
    } else {
        int j2 = idx - Bn*Tn*Dn;
        if (j2 < 2*G3*Dn) {
            int row = j2 >> 9, k = j2 & 511;
            float w = (row < G3) ? w_ih_f[row * 512 + k]
                                 : w_ih_b[(row - G3) * 512 + k];
            __nv_bfloat16 hi = __float2bfloat16(w);
            __nv_bfloat16 lo = __float2bfloat16(w - __bfloat162float(hi));
            __nv_bfloat16* dst = g_wext + (size_t)row * KE;
            dst[k] = hi; dst[512 + k] = hi; dst[1024 + k] = lo;
        }
    }
}

// ---------------- input-gate GEMM on HMMA + cp.async double buffer ----------------
// C[32768,1536] = A_ext @ W_ext^T + bias.  BM=128 BN=128 BK=32,
// 8 warps (4m x 2n), warp tile 32x64, fp32 accum, 2-stage cp.async pipeline.
__global__ void __launch_bounds__(256) xg_gemm_mma(const float* __restrict__ bfv,
                                                   const float* __restrict__ bbv) {
    __shared__ __align__(16) __nv_bfloat16 As[2][128][40];  // 40 = 32 + 8 pad
    __shared__ __align__(16) __nv_bfloat16 Bs[2][128][40];

    const int tid  = threadIdx.x;
    const int lane = tid & 31;
    const int wid  = tid >> 5;
    const int wm   = wid >> 1;
    const int wn   = wid & 1;
    const int col0 = blockIdx.x * 128;   // N base (12)
    const int row0 = blockIdx.y * 128;   // M base (256)

    const __nv_bfloat16* __restrict__ Abase = g_aext + (size_t)row0 * KA;
    const __nv_bfloat16* __restrict__ Bbase = g_wext + (size_t)col0 * KE;

    uint32_t sA = (uint32_t)__cvta_generic_to_shared(&As[0][0][0]);
    uint32_t sB = (uint32_t)__cvta_generic_to_shared(&Bs[0][0][0]);
    const uint32_t STG = 128 * 40 * 2;   // stage stride in bytes

    float d[2][8][4];
#pragma unroll
    for (int mt = 0; mt < 2; mt++)
#pragma unroll
        for (int nt = 0; nt < 8; nt++)
#pragma unroll
            for (int e = 0; e < 4; e++) d[mt][nt][e] = 0.f;

    // async-load assignment: thread t -> rows (t>>2, t>>2 + 64), 16B chunk (t&3)
    const int pr = tid >> 2;
    const int pq = (tid & 3) * 8;        // bf16 offset within 32-elem row
    const uint32_t smoff = (uint32_t)(pr * 40 + pq) * 2;

    // issue chunk `c` into stage `st`
    auto issue = [&](int c, int st) {
        int an = (c < 32) ? c : (c - 32);   // A reuses hi chunks for term 3
        const __nv_bfloat16* ap = Abase + (size_t)an * 32 + pq;
        const __nv_bfloat16* bp = Bbase + (size_t)c * 32 + pq;
        uint32_t da = sA + st * STG + smoff;
        uint32_t db = sB + st * STG + smoff;
#pragma unroll
        for (int s = 0; s < 2; s++) {
            cp_async16(da + s * (64 * 40 * 2), ap + (size_t)(pr + s * 64) * KA);
            cp_async16(db + s * (64 * 40 * 2), bp + (size_t)(pr + s * 64) * KE);
        }
        CP_COMMIT();
    };

    issue(0, 0);

    const int a_r = (lane & 15);
    const int a_c = (lane >> 4) * 8;
    const int b_r = (lane & 7) + ((lane >> 4) << 3);
    const int b_c = ((lane >> 3) & 1) * 8;

    for (int c = 0; c < 48; c++) {
        if (c < 47) { issue(c + 1, (c + 1) & 1); CP_WAIT(1); }
        else        { CP_WAIT(0); }
        __syncthreads();

        const uint32_t sAc = sA + (c & 1) * STG;
        const uint32_t sBc = sB + (c & 1) * STG;
#pragma unroll
        for (int ks = 0; ks < 2; ks++) {
            uint32_t af[2][4];
#pragma unroll
            for (int mt = 0; mt < 2; mt++) {
                int row = wm*32 + mt*16 + a_r;
                int col = ks*16 + a_c;
                ldsm4(af[mt], sAc + (uint32_t)(row * 40 + col) * 2);
            }
#pragma unroll
            for (int p = 0; p < 4; p++) {
                uint32_t bfr[4];
                int row = wn*64 + p*16 + b_r;
                int col = ks*16 + b_c;
                ldsm4(bfr, sBc + (uint32_t)(row * 40 + col) * 2);
#pragma unroll
                for (int mt = 0; mt < 2; mt++) {
                    mma16816(d[mt][2*p],     af[mt], bfr[0], bfr[1]);
                    mma16816(d[mt][2*p + 1], af[mt], bfr[2], bfr[3]);
                }
            }
        }
        __syncthreads();   // stage free for reuse before next issue
    }

    const int dir = (col0 >= G3) ? 1 : 0;
    const int j0  = col0 - dir * G3;
    const float* __restrict__ bias = dir ? bbv : bfv;
    float* __restrict__ outb = g_xg + (size_t)dir * XG_STRIDE;
#pragma unroll
    for (int nt = 0; nt < 8; nt++) {
        const int gn = j0 + wn*64 + nt*8 + (lane & 3) * 2;
        const float bx = bias[gn], by = bias[gn + 1];
#pragma unroll
        for (int mt = 0; mt < 2; mt++) {
            const int gm = row0 + wm*32 + mt*16 + (lane >> 2);
            float2 lo = make_float2(d[mt][nt][0] + bx, d[mt][nt][1] + by);
            float2 hi = make_float2(d[mt][nt][2] + bx, d[mt][nt][3] + by);
            *(float2*)(outb + (size_t)gm * G3 + gn)       = lo;
            *(float2*)(outb + (size_t)(gm + 8) * G3 + gn) = hi;
        }
    }
}

// ---------------- recurrent scan: cluster-4, split cluster barrier ----------------
// R12's proven barrier.cluster ordering, but arrive (release) at end of step t
// and wait (acquire) at top of step t+1 AFTER the h-independent xg prefetch,
// so xg DRAM latency overlaps peer skew.
__global__ void __launch_bounds__(256, 1) __cluster_dims__(4, 1, 1)
scan_kernel(const float* __restrict__ b_hh_f,
            const float* __restrict__ b_hh_b,
            const int*   __restrict__ lengths) {
    extern __shared__ __align__(16) float smem[];
    float* w_s = smem;                                   // [3][256][64]
    float* h_s = smem + SCAN_W_FLOATS;                   // [2][256][8]
    u64*  part = (u64*)(smem + SCAN_W_FLOATS + SCAN_H_FLOATS); // [128][6]

    const int myrank = blockIdx.x & 3;
    const int cid    = blockIdx.x >> 2;
    const int dir    = cid >> 4;
    const int bg     = cid & 15;
    const int b0     = bg * 8;

    const int tid = threadIdx.x;
    const int i   = tid & 63;
    const int q   = (tid >> 6) & 1;
    const int kh  = tid >> 7;
    const int gu  = myrank * 64 + i;

    {
        const float4* src = (const float4*)(g_wsc + (size_t)(dir * 4 + myrank) * SCAN_W_FLOATS);
        float4* dst = (float4*)w_s;
#pragma unroll
        for (int f = tid; f < SCAN_W_FLOATS / 4; f += 256) dst[f] = src[f];
        for (int f = tid; f < SCAN_H_FLOATS; f += 256) h_s[f] = 0.f;
    }
    const float* bh = dir ? b_hh_b : b_hh_f;
    const float bhr = bh[gu], bhz = bh[Hn + gu], bhn = bh[2 * Hn + gu];
    int lens[4];
#pragma unroll
    for (int j = 0; j < 4; j++) lens[j] = lengths[b0 + 4 * q + j];

    __syncthreads();
    CLUSTER_SYNC();   // peers' h buffers initialized before any DSMEM write

    const float* __restrict__ XG = g_xg + (size_t)dir * XG_STRIDE;
    const u64 Z = pack2(0.f, 0.f);

    for (int t = 0; t < Tn; t++) {
        const int buf = t & 1, nb = 1 - buf;

        // prefetch xg (h-independent) BEFORE waiting on peers
        float xv[4][3];
        int touts[4];
        if (!kh) {
#pragma unroll
            for (int j = 0; j < 4; j++) {
                int L = lens[j];
                int tsrc = dir ? ((t < L) ? (L - 1 - t) : t) : t;
                touts[j] = dir ? tsrc : t;
                const float* xg = XG + ((size_t)(b0 + 4 * q + j) * Tn + tsrc) * G3;
                xv[j][0] = xg[gu];
                xv[j][1] = xg[Hn + gu];
                xv[j][2] = xg[2 * Hn + gu];
            }
        }

        if (t > 0) CLUSTER_WAIT();   // acquire: peer h stores of step t-1 visible

        u64 ar0 = Z, ar1 = Z, az0 = Z, az1 = Z, an0 = Z, an1 = Z;
        const float* hb = h_s + buf * 2048 + q * 4 + kh * 128 * 8;
        const float* wp = w_s + kh * 128 * 64 + i;
#pragma unroll 4
        for (int k0 = 0; k0 < 128; k0++) {
            float wr = wp[0];
            float wz = wp[16384];
            float wn = wp[32768];
            ulonglong2 hv = *(const ulonglong2*)(hb + k0 * 8);
            u64 pr = pack2(wr, wr), pz = pack2(wz, wz), pn = pack2(wn, wn);
            ar0 = fma2(pr, hv.x, ar0); ar1 = fma2(pr, hv.y, ar1);
            az0 = fma2(pz, hv.x, az0); az1 = fma2(pz, hv.y, az1);
            an0 = fma2(pn, hv.x, an0); an1 = fma2(pn, hv.y, an1);
            wp += 64;
        }

        if (kh) {
            u64* pp = &part[(q * 64 + i) * 6];
            pp[0] = ar0; pp[1] = ar1; pp[2] = az0;
            pp[3] = az1; pp[4] = an0; pp[5] = an1;
        }
        __syncthreads();

        if (!kh) {
            const u64* pp = &part[(q * 64 + i) * 6];
            ar0 = add2(ar0, pp[0]); ar1 = add2(ar1, pp[1]);
            az0 = add2(az0, pp[2]); az1 = add2(az1, pp[3]);
            an0 = add2(an0, pp[4]); an1 = add2(an1, pp[5]);

            const float* hold = h_s + buf * 2048 + gu * 8 + q * 4;
            float ho[4] = {hold[0], hold[1], hold[2], hold[3]};
            float2 rA = unpack2(ar0), rB = unpack2(ar1);
            float2 zA = unpack2(az0), zB = unpack2(az1);
            float2 nA = unpack2(an0), nB = unpack2(an1);
            float arv[4] = {rA.x, rA.y, rB.x, rB.y};
            float azv[4] = {zA.x, zA.y, zB.x, zB.y};
            float anv[4] = {nA.x, nA.y, nB.x, nB.y};

            float hn4[4];
#pragma unroll
            for (int j = 0; j < 4; j++) {
                int b = 4 * q + j;
                int L = lens[j];
                float r = sigm(xv[j][0] + arv[j] + bhr);
                float z = sigm(xv[j][1] + azv[j] + bhz);
                float n = tanhf(xv[j][2] + r * (anv[j] + bhn));
                float hq = (1.f - z) * n + z * ho[j];
                bool  m  = (t < L);
                g_out[((size_t)(b0 + b) * Tn + touts[j]) * H2 + dir * Hn + gu] = m ? hq : 0.f;
                hn4[j] = m ? hq : ho[j];
            }

            if (t < Tn - 1) {
                u64 v0 = pack2(hn4[0], hn4[1]);
                u64 v1 = pack2(hn4[2], hn4[3]);
                float* hdst = h_s + nb * 2048 + gu * 8 + q * 4;
                *(u64*)hdst       = v0;          // local
                *(u64*)(hdst + 2) = v1;
                uint32_t laddr = (uint32_t)__cvta_generic_to_shared(hdst);
#pragma unroll
                for (int r2 = 0; r2 < 4; r2++) {
                    if (r2 != myrank) {
                        dsmem_st_u64(laddr,     r2, v0);
                        dsmem_st_u64(laddr + 8, r2, v1);
                    }
                }
            }
        }
        if (t < Tn - 1) CLUSTER_ARRIVE();   // release: h stores ordered for peers
    }
}

// ---------------- score MLP (8 rows per block) ----------------
__global__ void __launch_bounds__(256) mlp_kernel(const float* __restrict__ b1,
                                                  const float* __restrict__ w2,
                                                  const float* __restrict__ b2) {
    const int bt0 = blockIdx.x * 8;
    const int tid = threadIdx.x;
    const int k2 = tid & 31;
    const int rg = tid >> 5;
    __shared__ __align__(16) float srow[8][512];

#pragma unroll
    for (int f = tid; f < 1024; f += 256) {
        int row = f >> 7, h4 = f & 127;
        ((float4*)srow[row])[h4] =
            *(const float4*)(g_out + (size_t)(bt0 + row) * H2 + 4 * h4);
    }
    __syncthreads();

    const u64 Z = pack2(0.f, 0.f);
    u64 acc0 = Z, acc1 = Z;
    const float* __restrict__ w = g_w1t + 2 * k2;
#pragma unroll 4
    for (int h = 0; h < 256; h++) {
        u64 wv0 = *(const u64*)(w + h * 64);
        u64 wv1 = *(const u64*)(w + (h + 256) * 64);
        float s0 = srow[rg][h];
        float s1 = srow[rg][h + 256];
        acc0 = fma2(pack2(s0, s0), wv0, acc0);
        acc1 = fma2(pack2(s1, s1), wv1, acc1);
    }
    u64 acc = add2(acc0, acc1);
    float2 a0 = unpack2(acc);
    float b1a = b1[2 * k2], b1b = b1[2 * k2 + 1];
    float w2a = w2[2 * k2], w2b = w2[2 * k2 + 1];
    float p0 = fmaxf(a0.x + b1a, 0.f) * w2a + fmaxf(a0.y + b1b, 0.f) * w2b;
#pragma unroll
    for (int off = 16; off > 0; off >>= 1)
        p0 += __shfl_down_sync(0xffffffffu, p0, off);
    if (k2 == 0) g_scores[bt0 + rg] = p0 + b2[0];
}

// ---------------- softmax + top-3 attention + heads ----------------
__global__ void final_kernel(const int*   __restrict__ lengths,
                             const float* __restrict__ temp_p,
                             const float* __restrict__ w_tens,
                             const float* __restrict__ b_tens,
                             const float* __restrict__ w_ones,
                             const float* __restrict__ b_ones,
                             float* __restrict__ out) {
    const int bb  = blockIdx.x;
    const int tid = threadIdx.x;
    __shared__ float sp[Tn];
    __shared__ float sred[Tn];
    __shared__ __align__(16) float sfeat[H2];
    __shared__ int   s_topi[3];
    __shared__ float s_topw[3];
    __shared__ int   s_fallback;

    const int len = lengths[bb];
    float temp = fminf(fmaxf(temp_p[0], 0.001f), 10.f);

    float sc = (tid < len) ? (g_scores[bb * Tn + tid] / temp) : -INFINITY;

    sred[tid] = sc; __syncthreads();
    for (int s = 128; s > 0; s >>= 1) {
        if (tid < s) sred[tid] = fmaxf(sred[tid], sred[tid + s]);
        __syncthreads();
    }
    float mx = sred[0]; __syncthreads();

    float e = (tid < len) ? expf(sc - mx) : 0.f;
    sred[tid] = e; __syncthreads();
    for (int s = 128; s > 0; s >>= 1) {
        if (tid < s) sred[tid] += sred[tid + s];
        __syncthreads();
    }
    float denom = sred[0];
    sp[tid] = e / denom;
    __syncthreads();

    if (tid == 0) {
        int k_act = (len < 3) ? len : 3;
        int i0 = -1, i1 = -1, i2 = -1;
        int pi[3]; float pv[3];
        for (int r = 0; r < 3; r++) {
            float best = -1.f; int bi = 0;
            for (int t2 = 0; t2 < Tn; t2++) {
                if (t2 == i0 || t2 == i1 || t2 == i2) continue;
                float v = sp[t2];
                if (v > best) { best = v; bi = t2; }
            }
            pi[r] = bi; pv[r] = best;
            if (r == 0) i0 = bi; else if (r == 1) i1 = bi; else i2 = bi;
        }
        float vsum = 0.f;
        for (int r = 0; r < 3; r++) if (r < k_act) vsum += pv[r];
        if (vsum > 1e-8f) {
            s_fallback = 0;
            float dv = fmaxf(vsum, 1e-8f);
            for (int r = 0; r < 3; r++) {
                s_topi[r] = pi[r];
                s_topw[r] = (r < k_act) ? (pv[r] / dv) : 0.f;
            }
        } else {
            s_fallback = 1;
        }
    }
    __syncthreads();

    for (int h = tid; h < H2; h += 256) {
        float acc = 0.f;
        if (!s_fallback) {
#pragma unroll
            for (int r = 0; r < 3; r++) {
                float w = s_topw[r];
                if (w != 0.f)
                    acc += w * g_out[((size_t)(bb * Tn + s_topi[r])) * H2 + h];
            }
        } else {
            for (int t2 = 0; t2 < len; t2++)
                acc += g_out[((size_t)(bb * Tn + t2)) * H2 + h];
            acc /= ((float)len + 1e-8f);
        }
        sfeat[h] = acc;
    }
    __syncthreads();

    if (tid < 21) {
        const float* wrow; float bias;
        if (tid < 11) { wrow = w_tens + (size_t)tid * H2;        bias = b_tens[tid]; }
        else          { wrow = w_ones + (size_t)(tid - 11) * H2; bias = b_ones[tid - 11]; }
        float acc = bias;
#pragma unroll 8
        for (int h = 0; h < H2; h++) acc += sfeat[h] * wrow[h];
        if (tid < 11) out[bb * 11 + tid] = acc;
        else          out[Bn * 11 + bb * 10 + (tid - 11)] = acc;
    }
}

// ---------------- launch ----------------
extern "C" void kernel_launch(void* const* d_in, const int* in_sizes, int n_in,
                              void* d_out, int out_size) {
    const float* feats   = (const float*)d_in[0];
    const int*   lengths = (const int*)  d_in[1];
    const float* temp    = (const float*)d_in[2];
    const float* w_ih_f  = (const float*)d_in[3];
    const float* w_hh_f  = (const float*)d_in[4];
    const float* b_ih_f  = (const float*)d_in[5];
    const float* b_hh_f  = (const float*)d_in[6];
    const float* w_ih_b  = (const float*)d_in[7];
    const float* w_hh_b  = (const float*)d_in[8];
    const float* b_ih_b  = (const float*)d_in[9];
    const float* b_hh_b  = (const float*)d_in[10];
    const float* w1      = (const float*)d_in[11];
    const float* b1      = (const float*)d_in[12];
    const float* w2      = (const float*)d_in[13];
    const float* b2      = (const float*)d_in[14];
    const float* w_tens  = (const float*)d_in[15];
    const float* b_tens  = (const float*)d_in[16];
    const float* w_ones  = (const float*)d_in[17];
    const float* b_ones  = (const float*)d_in[18];
    float* out = (float*)d_out;

    cudaFuncSetAttribute(scan_kernel,
        cudaFuncAttributeMaxDynamicSharedMemorySize, SCAN_SMEM_BYTES);

    // slot 0
    prep_kernel<<<1536, 256>>>(w_hh_f, w_hh_b, w1);
    // slot 1
    {
        int total = Bn*Tn*Dn + 2*G3*Dn;
        prep_split<<<(total + 255) / 256, 256>>>(feats, w_ih_f, w_ih_b);
    }
    // slot 2
    dummy_kernel<<<1, 32>>>();
    // slot 3 (profiler lands here -> measure cp.async GEMM)
    {
        dim3 g((2 * G3) / 128, Bn * Tn / 128);   // (12, 256)
        xg_gemm_mma<<<g, 256>>>(b_ih_f, b_ih_b);
    }
    // slot 4
    scan_kernel<<<128, 256, SCAN_SMEM_BYTES>>>(b_hh_f, b_hh_b, lengths);
    // slot 5
    mlp_kernel<<<Bn * Tn / 8, 256>>>(b1, w2, b2);
    // slot 6
    final_kernel<<<Bn, 256>>>(lengths, temp, w_tens, b_tens, w_ones, b_ones, out);
}

// round 16
// speedup vs baseline: 1.7420x; 1.0111x over previous
#include <cuda_runtime.h>
#include <cuda_bf16.h>
#include <math.h>
#include <stdint.h>

typedef unsigned long long u64;

#define Bn 128
#define Tn 256
#define Dn 512
#define Hn 256
#define G3 768    // 3*H
#define H2 512    // 2*H
#define KE 1536   // extended K (B operand; A reuses hi chunk)
#define KA 1024   // A operand stored K: [hi | lo]
#define XG_STRIDE (Bn*Tn*G3)   // 25,165,824

// scan smem layout: weights [3][256][64]f | h [2][256][8]f | part [128][6]u64 | mbar
#define SCAN_W_FLOATS (3*256*64)            // 49152
#define SCAN_H_FLOATS (2*256*8)             // 4096
#define SCAN_P_U64    (128*6)               // 768
#define SCAN_MBAR_OFF ((SCAN_W_FLOATS + SCAN_H_FLOATS)*4 + SCAN_P_U64*8)  // 219136
#define SCAN_SMEM_BYTES (SCAN_MBAR_OFF + 16)

// gemm smem: 3 stages x (A 10240B + B 10240B)
#define GEMM_STAGE_BYTES 20480
#define GEMM_SMEM_BYTES  (3 * GEMM_STAGE_BYTES)   // 61440

// ---------------- device scratch ----------------
__device__ float g_xg[2*Bn*Tn*G3];         // [dir][b][t][3H] input gates (+b_ih)
__device__ __nv_bfloat16 g_aext[(size_t)Bn*Tn*KA];  // [bt][KA]  split feats (hi|lo)
__device__ __nv_bfloat16 g_wext[2*G3*KE];           // [gate2dir][KE] split w_ih (hi|hi|lo)
__device__ float g_wsc[2*4*SCAN_W_FLOATS]; // [dir][rank][3][256][64] scan weights
__device__ float g_out[Bn*Tn*H2];          // [b][t][2H]
__device__ float g_scores[Bn*Tn];          // [b][t]
__device__ float g_w1t[H2*64];             // [h][o] w1 transposed

// ---------------- f32x2 helpers ----------------
__device__ __forceinline__ u64 fma2(u64 a, u64 b, u64 c) {
    u64 d;
    asm("fma.rn.f32x2 %0, %1, %2, %3;" : "=l"(d) : "l"(a), "l"(b), "l"(c));
    return d;
}
__device__ __forceinline__ u64 add2(u64 a, u64 b) {
    u64 d;
    asm("add.rn.f32x2 %0, %1, %2;" : "=l"(d) : "l"(a), "l"(b));
    return d;
}
__device__ __forceinline__ u64 pack2(float x, float y) {
    u64 d;
    asm("mov.b64 %0, {%1, %2};" : "=l"(d) : "f"(x), "f"(y));
    return d;
}
__device__ __forceinline__ float2 unpack2(u64 v) {
    float2 r;
    asm("mov.b64 {%0, %1}, %2;" : "=f"(r.x), "=f"(r.y) : "l"(v));
    return r;
}
__device__ __forceinline__ float sigm(float x) { return 1.f / (1.f + expf(-x)); }
// fast approx gates (MUFU-based): |err| ~1e-6..1e-5, fine vs 1e-3 tolerance
__device__ __forceinline__ float sigm_fast(float x) {
    float e;
    asm("ex2.approx.f32 %0, %1;" : "=f"(e) : "f"(x * -1.44269504f));
    float r;
    asm("rcp.approx.f32 %0, %1;" : "=f"(r) : "f"(1.f + e));
    return r;
}
__device__ __forceinline__ float tanh_fast(float x) {
    float y;
    asm("tanh.approx.f32 %0, %1;" : "=f"(y) : "f"(x));
    return y;
}

__device__ __forceinline__ void dsmem_st_u64(uint32_t laddr, int trank, u64 v) {
    asm volatile(
        "{\n\t.reg .b32 ra;\n\t"
        "mapa.shared::cluster.u32 ra, %0, %1;\n\t"
        "st.shared::cluster.b64 [ra], %2;\n\t}"
        :: "r"(laddr), "r"(trank), "l"(v) : "memory");
}
// EXPLICIT cluster-scope release arrive (R14 bug: default sem is release.cta,
// which does NOT order st.shared::cluster for peer-CTA observers).
__device__ __forceinline__ void mbar_arrive_rel_cluster(uint32_t mbar_laddr, int trank) {
    asm volatile(
        "{\n\t.reg .b32 ra;\n\t"
        "mapa.shared::cluster.u32 ra, %0, %1;\n\t"
        "mbarrier.arrive.release.cluster.shared::cluster.b64 _, [ra];\n\t}"
        :: "r"(mbar_laddr), "r"(trank) : "memory");
}
__device__ __forceinline__ void mbar_init(uint32_t mbar, uint32_t cnt) {
    asm volatile("mbarrier.init.shared.b64 [%0], %1;" :: "r"(mbar), "r"(cnt) : "memory");
}
__device__ __forceinline__ void mbar_wait_acq_cluster(uint32_t mbar, uint32_t parity) {
    uint32_t done;
    asm volatile(
        "{\n\t.reg .pred p;\n\t"
        "mbarrier.try_wait.parity.acquire.cluster.shared::cta.b64 p, [%1], %2;\n\t"
        "selp.b32 %0, 1, 0, p;\n\t}"
        : "=r"(done) : "r"(mbar), "r"(parity) : "memory");
    if (!done) {
        asm volatile(
            "{\n\t.reg .pred P1;\n\t"
            "W_%=:\n\t"
            "mbarrier.try_wait.parity.acquire.cluster.shared::cta.b64 P1, [%0], %1, 0x989680;\n\t"
            "@P1 bra.uni D_%=;\n\t"
            "bra.uni W_%=;\n\t"
            "D_%=:\n\t}"
            :: "r"(mbar), "r"(parity) : "memory");
    }
}
#define CLUSTER_SYNC() do { \
    asm volatile("barrier.cluster.arrive.aligned;" ::: "memory"); \
    asm volatile("barrier.cluster.wait.aligned;"   ::: "memory"); } while (0)

// ---------------- mma.sync helpers ----------------
__device__ __forceinline__ void ldsm4(uint32_t* r, uint32_t addr) {
    asm volatile("ldmatrix.sync.aligned.m8n8.x4.shared.b16 {%0,%1,%2,%3}, [%4];"
        : "=r"(r[0]), "=r"(r[1]), "=r"(r[2]), "=r"(r[3]) : "r"(addr));
}
__device__ __forceinline__ void mma16816(float* d, const uint32_t* a,
                                         uint32_t b0, uint32_t b1) {
    asm volatile(
        "mma.sync.aligned.m16n8k16.row.col.f32.bf16.bf16.f32 "
        "{%0,%1,%2,%3}, {%4,%5,%6,%7}, {%8,%9}, {%0,%1,%2,%3};"
        : "+f"(d[0]), "+f"(d[1]), "+f"(d[2]), "+f"(d[3])
        : "r"(a[0]), "r"(a[1]), "r"(a[2]), "r"(a[3]), "r"(b0), "r"(b1));
}
__device__ __forceinline__ void cp_async16(uint32_t smem_dst, const void* gmem_src) {
    asm volatile("cp.async.cg.shared.global [%0], [%1], 16;"
        :: "r"(smem_dst), "l"(gmem_src) : "memory");
}
#define CP_COMMIT()  asm volatile("cp.async.commit_group;" ::: "memory")
#define CP_WAIT(n)   asm volatile("cp.async.wait_group %0;" :: "n"(n) : "memory")

// ---------------- dummy (profiler slot positioning) ----------------
__global__ void dummy_kernel() {}

// ---------------- prep: scan weight relayout + w1t ----------------
__global__ void prep_kernel(const float* __restrict__ w_hh_f,
                            const float* __restrict__ w_hh_b,
                            const float* __restrict__ w1) {
    int idx = blockIdx.x * blockDim.x + threadIdx.x;
    if (idx < 2*4*SCAN_W_FLOATS) {
        int i = idx & 63;
        int t1 = idx >> 6;
        int k = t1 & 255;
        int t2 = t1 >> 8;
        int g = t2 % 3;
        int t3 = t2 / 3;
        int r = t3 & 3;
        int d = t3 >> 2;
        int row = g * 256 + r * 64 + i;
        const float* src = d ? w_hh_b : w_hh_f;
        g_wsc[idx] = src[row * 256 + k];
    }
    if (idx < 64 * H2) {
        int o = idx / H2;
        int h = idx % H2;
        g_w1t[h * 64 + o] = w1[idx];
    }
}

// ---------------- prep: bf16 hi/lo split ----------------
__global__ void prep_split(const float* __restrict__ feats,
                           const float* __restrict__ w_ih_f,
                           const float* __restrict__ w_ih_b) {
    int idx = blockIdx.x * blockDim.x + threadIdx.x;
    if (idx < Bn*Tn*Dn) {
        int row = idx >> 9, k = idx & 511;
        float a = feats[idx];
        __nv_bfloat16 hi = __float2bfloat16(a);
        __nv_bfloat16 lo = __float2bfloat16(a - __bfloat162float(hi));
        __nv_bfloat16* dst = g_aext + (size_t)row * KA;
        dst[k] = hi; dst[512 + k] = lo;
    } else {
        int j2 = idx - Bn*Tn*Dn;
        if (j2 < 2*G3*Dn) {
            int row = j2 >> 9, k = j2 & 511;
            float w = (row < G3) ? w_ih_f[row * 512 + k]
                                 : w_ih_b[(row - G3) * 512 + k];
            __nv_bfloat16 hi = __float2bfloat16(w);
            __nv_bfloat16 lo = __float2bfloat16(w - __bfloat162float(hi));
            __nv_bfloat16* dst = g_wext + (size_t)row * KE;
            dst[k] = hi; dst[512 + k] = hi; dst[1024 + k] = lo;
        }
    }
}

// ---------------- input-gate GEMM: HMMA + 3-stage cp.async (1 sync/chunk) ----------------
__global__ void __launch_bounds__(256) xg_gemm_mma(const float* __restrict__ bfv,
                                                   const float* __restrict__ bbv) {
    extern __shared__ __align__(16) char gsm[];

    const int tid  = threadIdx.x;
    const int lane = tid & 31;
    const int wid  = tid >> 5;
    const int wm   = wid >> 1;
    const int wn   = wid & 1;
    const int col0 = blockIdx.x * 128;   // N base (12)
    const int row0 = blockIdx.y * 128;   // M base (256)

    const __nv_bfloat16* __restrict__ Abase = g_aext + (size_t)row0 * KA;
    const __nv_bfloat16* __restrict__ Bbase = g_wext + (size_t)col0 * KE;

    const uint32_t sBase = (uint32_t)__cvta_generic_to_shared(gsm);

    float d[2][8][4];
#pragma unroll
    for (int mt = 0; mt < 2; mt++)
#pragma unroll
        for (int nt = 0; nt < 8; nt++)
#pragma unroll
            for (int e = 0; e < 4; e++) d[mt][nt][e] = 0.f;

    const int pr = tid >> 2;
    const int pq = (tid & 3) * 8;
    const uint32_t smoff = (uint32_t)(pr * 40 + pq) * 2;

    auto issue = [&](int c, int st) {
        int an = (c < 32) ? c : (c - 32);
        const __nv_bfloat16* ap = Abase + (size_t)an * 32 + pq;
        const __nv_bfloat16* bp = Bbase + (size_t)c * 32 + pq;
        uint32_t da = sBase + st * GEMM_STAGE_BYTES + smoff;
        uint32_t db = da + 10240;
#pragma unroll
        for (int s = 0; s < 2; s++) {
            cp_async16(da + s * (64 * 40 * 2), ap + (size_t)(pr + s * 64) * KA);
            cp_async16(db + s * (64 * 40 * 2), bp + (size_t)(pr + s * 64) * KE);
        }
        CP_COMMIT();
    };

    issue(0, 0);
    issue(1, 1);

    const int a_r = (lane & 15);
    const int a_c = (lane >> 4) * 8;
    const int b_r = (lane & 7) + ((lane >> 4) << 3);
    const int b_c = ((lane >> 3) & 1) * 8;

    for (int c = 0; c < 48; c++) {
        if (c < 47) CP_WAIT(1);
        else        CP_WAIT(0);
        __syncthreads();
        if (c + 2 < 48) issue(c + 2, (c + 2) % 3);

        const uint32_t sAc = sBase + (c % 3) * GEMM_STAGE_BYTES;
        const uint32_t sBc = sAc + 10240;
#pragma unroll
        for (int ks = 0; ks < 2; ks++) {
            uint32_t af[2][4];
#pragma unroll
            for (int mt = 0; mt < 2; mt++) {
                int row = wm*32 + mt*16 + a_r;
                int col = ks*16 + a_c;
                ldsm4(af[mt], sAc + (uint32_t)(row * 40 + col) * 2);
            }
#pragma unroll
            for (int p = 0; p < 4; p++) {
                uint32_t bfr[4];
                int row = wn*64 + p*16 + b_r;
                int col = ks*16 + b_c;
                ldsm4(bfr, sBc + (uint32_t)(row * 40 + col) * 2);
#pragma unroll
                for (int mt = 0; mt < 2; mt++) {
                    mma16816(d[mt][2*p],     af[mt], bfr[0], bfr[1]);
                    mma16816(d[mt][2*p + 1], af[mt], bfr[2], bfr[3]);
                }
            }
        }
    }

    const int dir = (col0 >= G3) ? 1 : 0;
    const int j0  = col0 - dir * G3;
    const float* __restrict__ bias = dir ? bbv : bfv;
    float* __restrict__ outb = g_xg + (size_t)dir * XG_STRIDE;
#pragma unroll
    for (int nt = 0; nt < 8; nt++) {
        const int gn = j0 + wn*64 + nt*8 + (lane & 3) * 2;
        const float bx = bias[gn], by = bias[gn + 1];
#pragma unroll
        for (int mt = 0; mt < 2; mt++) {
            const int gm = row0 + wm*32 + mt*16 + (lane >> 2);
            float2 lo = make_float2(d[mt][nt][0] + bx, d[mt][nt][1] + by);
            float2 hi = make_float2(d[mt][nt][2] + bx, d[mt][nt][3] + by);
            *(float2*)(outb + (size_t)gm * G3 + gn)       = lo;
            *(float2*)(outb + (size_t)(gm + 8) * G3 + gn) = hi;
        }
    }
}

// ---------------- recurrent scan: cluster-4, cluster-scope mbarrier sync ----------------
// Per step: prefetch xg; compute OWN-rank 64 k-iters (local h, ordered by the
// end-of-step __syncthreads); mbarrier wait (acquire.cluster); remaining k;
// partial-reduce; epilogue w/ approx gates; DSMEM h push; arrive.release.cluster x4.
__global__ void __launch_bounds__(256, 1) __cluster_dims__(4, 1, 1)
scan_kernel(const float* __restrict__ b_hh_f,
            const float* __restrict__ b_hh_b,
            const int*   __restrict__ lengths) {
    extern __shared__ __align__(16) float smem[];
    float* w_s = smem;                                   // [3][256][64]
    float* h_s = smem + SCAN_W_FLOATS;                   // [2][256][8]
    u64*  part = (u64*)(smem + SCAN_W_FLOATS + SCAN_H_FLOATS); // [128][6]
    uint32_t mbar = (uint32_t)__cvta_generic_to_shared((char*)smem + SCAN_MBAR_OFF);

    const int myrank = blockIdx.x & 3;
    const int cid    = blockIdx.x >> 2;
    const int dir    = cid >> 4;
    const int bg     = cid & 15;
    const int b0     = bg * 8;

    const int tid = threadIdx.x;
    const int i   = tid & 63;
    const int q   = (tid >> 6) & 1;
    const int kh  = tid >> 7;
    const int gu  = myrank * 64 + i;

    // does this thread's k-half [128kh,128kh+128) contain own units [64r,64r+64)?
    const bool hasOwn = ((myrank >> 1) == kh);
    const int  oStart = (myrank & 1) * 64;   // own segment local offset (if hasOwn)

    {
        const float4* src = (const float4*)(g_wsc + (size_t)(dir * 4 + myrank) * SCAN_W_FLOATS);
        float4* dst = (float4*)w_s;
#pragma unroll
        for (int f = tid; f < SCAN_W_FLOATS / 4; f += 256) dst[f] = src[f];
        for (int f = tid; f < SCAN_H_FLOATS; f += 256) h_s[f] = 0.f;
    }
    if (tid == 0) mbar_init(mbar, 512);   // 128 producers x 4 CTAs
    const float* bh = dir ? b_hh_b : b_hh_f;
    const float bhr = bh[gu], bhz = bh[Hn + gu], bhn = bh[2 * Hn + gu];
    int lens[4];
#pragma unroll
    for (int j = 0; j < 4; j++) lens[j] = lengths[b0 + 4 * q + j];

    __syncthreads();
    CLUSTER_SYNC();   // peers' h buffers + mbar initialized before any remote op

    const float* __restrict__ XG = g_xg + (size_t)dir * XG_STRIDE;
    const u64 Z = pack2(0.f, 0.f);

    for (int t = 0; t < Tn; t++) {
        const int buf = t & 1, nb = 1 - buf;

        // xg prefetch (h-independent)
        float xv[4][3];
        int touts[4];
        if (!kh) {
#pragma unroll
            for (int j = 0; j < 4; j++) {
                int L = lens[j];
                int tsrc = dir ? ((t < L) ? (L - 1 - t) : t) : t;
                touts[j] = dir ? tsrc : t;
                const float* xg = XG + ((size_t)(b0 + 4 * q + j) * Tn + tsrc) * G3;
                xv[j][0] = xg[gu];
                xv[j][1] = xg[Hn + gu];
                xv[j][2] = xg[2 * Hn + gu];
            }
        }

        u64 ar0 = Z, ar1 = Z, az0 = Z, az1 = Z, an0 = Z, an1 = Z;
        auto seg64 = [&](int s0) {
            const float* wp = w_s + (kh * 128 + s0) * 64 + i;
            const float* hb = h_s + buf * 2048 + (kh * 128 + s0) * 8 + q * 4;
#pragma unroll 4
            for (int k0 = 0; k0 < 64; k0++) {
                float wr = wp[0];
                float wz = wp[16384];
                float wn = wp[32768];
                ulonglong2 hv = *(const ulonglong2*)(hb + k0 * 8);
                u64 pr = pack2(wr, wr), pz = pack2(wz, wz), pn = pack2(wn, wn);
                ar0 = fma2(pr, hv.x, ar0); ar1 = fma2(pr, hv.y, ar1);
                az0 = fma2(pz, hv.x, az0); az1 = fma2(pz, hv.y, az1);
                an0 = fma2(pn, hv.x, an0); an1 = fma2(pn, hv.y, an1);
                wp += 64;
            }
        };

        if (hasOwn) {
            seg64(oStart);                       // own-rank h: ready locally
            if (t > 0) mbar_wait_acq_cluster(mbar, (t - 1) & 1);
            seg64(oStart ^ 64);
        } else {
            if (t > 0) mbar_wait_acq_cluster(mbar, (t - 1) & 1);
            seg64(0);
            seg64(64);
        }

        if (kh) {
            u64* pp = &part[(q * 64 + i) * 6];
            pp[0] = ar0; pp[1] = ar1; pp[2] = az0;
            pp[3] = az1; pp[4] = an0; pp[5] = an1;
        }
        __syncthreads();

        if (!kh) {
            const u64* pp = &part[(q * 64 + i) * 6];
            ar0 = add2(ar0, pp[0]); ar1 = add2(ar1, pp[1]);
            az0 = add2(az0, pp[2]); az1 = add2(az1, pp[3]);
            an0 = add2(an0, pp[4]); an1 = add2(an1, pp[5]);

            const float* hold = h_s + buf * 2048 + gu * 8 + q * 4;
            float ho[4] = {hold[0], hold[1], hold[2], hold[3]};
            float2 rA = unpack2(ar0), rB = unpack2(ar1);
            float2 zA = unpack2(az0), zB = unpack2(az1);
            float2 nA = unpack2(an0), nB = unpack2(an1);
            float arv[4] = {rA.x, rA.y, rB.x, rB.y};
            float azv[4] = {zA.x, zA.y, zB.x, zB.y};
            float anv[4] = {nA.x, nA.y, nB.x, nB.y};

            float hn4[4], hout[4];
#pragma unroll
            for (int j = 0; j < 4; j++) {
                int L = lens[j];
                float r = sigm_fast(xv[j][0] + arv[j] + bhr);
                float z = sigm_fast(xv[j][1] + azv[j] + bhz);
                float n = tanh_fast(xv[j][2] + r * (anv[j] + bhn));
                float hq = (1.f - z) * n + z * ho[j];
                bool  m  = (t < L);
                hout[j] = m ? hq : 0.f;
                hn4[j]  = m ? hq : ho[j];
            }

            if (t < Tn - 1) {
                u64 v0 = pack2(hn4[0], hn4[1]);
                u64 v1 = pack2(hn4[2], hn4[3]);
                float* hdst = h_s + nb * 2048 + gu * 8 + q * 4;
                *(u64*)hdst       = v0;          // local
                *(u64*)(hdst + 2) = v1;
                uint32_t laddr = (uint32_t)__cvta_generic_to_shared(hdst);
#pragma unroll
                for (int r2 = 0; r2 < 4; r2++) {
                    if (r2 != myrank) {
                        dsmem_st_u64(laddr,     r2, v0);
                        dsmem_st_u64(laddr + 8, r2, v1);
                    }
                }
#pragma unroll
                for (int r2 = 0; r2 < 4; r2++)
                    mbar_arrive_rel_cluster(mbar, r2);   // release: h stores visible
            }
            // g_out stores off the critical chain (after arrive)
#pragma unroll
            for (int j = 0; j < 4; j++)
                g_out[((size_t)(b0 + 4 * q + j) * Tn + touts[j]) * H2 + dir * Hn + gu] = hout[j];
        }
        // intra-CTA: local h visible to own-segment readers of next step
        if (t < Tn - 1) __syncthreads();
    }
}

// ---------------- score MLP: 32 rows/block, 4 rows/thread, L1-resident w1t ----------------
__global__ void __launch_bounds__(256) mlp_kernel(const float* __restrict__ b1,
                                                  const float* __restrict__ w2,
                                                  const float* __restrict__ b2) {
    const int bt0 = blockIdx.x * 32;
    const int tid = threadIdx.x;
    const int k2 = tid & 31;          // output pair 2k2, 2k2+1
    const int rg = tid >> 5;          // warp -> rows 4rg .. 4rg+3
    const int r0 = bt0 + rg * 4;

    const u64 Z = pack2(0.f, 0.f);
    u64 acc[4] = {Z, Z, Z, Z};
    const float* __restrict__ w = g_w1t + 2 * k2;
    const float* __restrict__ row0p = g_out + (size_t)r0 * H2;

#pragma unroll 2
    for (int h4 = 0; h4 < 128; h4++) {
        u64 wv[4];
#pragma unroll
        for (int e = 0; e < 4; e++)
            wv[e] = *(const u64*)(w + (4 * h4 + e) * 64);
#pragma unroll
        for (int j = 0; j < 4; j++) {
            float4 s4 = *(const float4*)(row0p + (size_t)j * H2 + 4 * h4);
            acc[j] = fma2(pack2(s4.x, s4.x), wv[0], acc[j]);
            acc[j] = fma2(pack2(s4.y, s4.y), wv[1], acc[j]);
            acc[j] = fma2(pack2(s4.z, s4.z), wv[2], acc[j]);
            acc[j] = fma2(pack2(s4.w, s4.w), wv[3], acc[j]);
        }
    }

    const float b1a = b1[2 * k2], b1b = b1[2 * k2 + 1];
    const float w2a = w2[2 * k2], w2b = w2[2 * k2 + 1];
    float p[4];
#pragma unroll
    for (int j = 0; j < 4; j++) {
        float2 a = unpack2(acc[j]);
        p[j] = fmaxf(a.x + b1a, 0.f) * w2a + fmaxf(a.y + b1b, 0.f) * w2b;
    }
#pragma unroll
    for (int off = 16; off > 0; off >>= 1)
#pragma unroll
        for (int j = 0; j < 4; j++)
            p[j] += __shfl_down_sync(0xffffffffu, p[j], off);
    if (k2 == 0) {
        float bb = b2[0];
#pragma unroll
        for (int j = 0; j < 4; j++) g_scores[r0 + j] = p[j] + bb;
    }
}

// ---------------- softmax + top-3 attention + heads ----------------
__global__ void final_kernel(const int*   __restrict__ lengths,
                             const float* __restrict__ temp_p,
                             const float* __restrict__ w_tens,
                             const float* __restrict__ b_tens,
                             const float* __restrict__ w_ones,
                             const float* __restrict__ b_ones,
                             float* __restrict__ out) {
    const int bb  = blockIdx.x;
    const int tid = threadIdx.x;
    __shared__ float sp[Tn];
    __shared__ float sred[Tn];
    __shared__ __align__(16) float sfeat[H2];
    __shared__ int   s_topi[3];
    __shared__ float s_topw[3];
    __shared__ int   s_fallback;

    const int len = lengths[bb];
    float temp = fminf(fmaxf(temp_p[0], 0.001f), 10.f);

    float sc = (tid < len) ? (g_scores[bb * Tn + tid] / temp) : -INFINITY;

    sred[tid] = sc; __syncthreads();
    for (int s = 128; s > 0; s >>= 1) {
        if (tid < s) sred[tid] = fmaxf(sred[tid], sred[tid + s]);
        __syncthreads();
    }
    float mx = sred[0]; __syncthreads();

    float e = (tid < len) ? expf(sc - mx) : 0.f;
    sred[tid] = e; __syncthreads();
    for (int s = 128; s > 0; s >>= 1) {
        if (tid < s) sred[tid] += sred[tid + s];
        __syncthreads();
    }
    float denom = sred[0];
    sp[tid] = e / denom;
    __syncthreads();

    if (tid == 0) {
        int k_act = (len < 3) ? len : 3;
        int i0 = -1, i1 = -1, i2 = -1;
        int pi[3]; float pv[3];
        for (int r = 0; r < 3; r++) {
            float best = -1.f; int bi = 0;
            for (int t2 = 0; t2 < Tn; t2++) {
                if (t2 == i0 || t2 == i1 || t2 == i2) continue;
                float v = sp[t2];
                if (v > best) { best = v; bi = t2; }
            }
            pi[r] = bi; pv[r] = best;
            if (r == 0) i0 = bi; else if (r == 1) i1 = bi; else i2 = bi;
        }
        float vsum = 0.f;
        for (int r = 0; r < 3; r++) if (r < k_act) vsum += pv[r];
        if (vsum > 1e-8f) {
            s_fallback = 0;
            float dv = fmaxf(vsum, 1e-8f);
            for (int r = 0; r < 3; r++) {
                s_topi[r] = pi[r];
                s_topw[r] = (r < k_act) ? (pv[r] / dv) : 0.f;
            }
        } else {
            s_fallback = 1;
        }
    }
    __syncthreads();

    for (int h = tid; h < H2; h += 256) {
        float acc = 0.f;
        if (!s_fallback) {
#pragma unroll
            for (int r = 0; r < 3; r++) {
                float w = s_topw[r];
                if (w != 0.f)
                    acc += w * g_out[((size_t)(bb * Tn + s_topi[r])) * H2 + h];
            }
        } else {
            for (int t2 = 0; t2 < len; t2++)
                acc += g_out[((size_t)(bb * Tn + t2)) * H2 + h];
            acc /= ((float)len + 1e-8f);
        }
        sfeat[h] = acc;
    }
    __syncthreads();

    if (tid < 21) {
        const float* wrow; float bias;
        if (tid < 11) { wrow = w_tens + (size_t)tid * H2;        bias = b_tens[tid]; }
        else          { wrow = w_ones + (size_t)(tid - 11) * H2; bias = b_ones[tid - 11]; }
        float acc = bias;
#pragma unroll 8
        for (int h = 0; h < H2; h++) acc += sfeat[h] * wrow[h];
        if (tid < 11) out[bb * 11 + tid] = acc;
        else          out[Bn * 11 + bb * 10 + (tid - 11)] = acc;
    }
}

// ---------------- launch ----------------
extern "C" void kernel_launch(void* const* d_in, const int* in_sizes, int n_in,
                              void* d_out, int out_size) {
    const float* feats   = (const float*)d_in[0];
    const int*   lengths = (const int*)  d_in[1];
    const float* temp    = (const float*)d_in[2];
    const float* w_ih_f  = (const float*)d_in[3];
    const float* w_hh_f  = (const float*)d_in[4];
    const float* b_ih_f  = (const float*)d_in[5];
    const float* b_hh_f  = (const float*)d_in[6];
    const float* w_ih_b  = (const float*)d_in[7];
    const float* w_hh_b  = (const float*)d_in[8];
    const float* b_ih_b  = (const float*)d_in[9];
    const float* b_hh_b  = (const float*)d_in[10];
    const float* w1      = (const float*)d_in[11];
    const float* b1      = (const float*)d_in[12];
    const float* w2      = (const float*)d_in[13];
    const float* b2      = (const float*)d_in[14];
    const float* w_tens  = (const float*)d_in[15];
    const float* b_tens  = (const float*)d_in[16];
    const float* w_ones  = (const float*)d_in[17];
    const float* b_ones  = (const float*)d_in[18];
    float* out = (float*)d_out;

    cudaFuncSetAttribute(scan_kernel,
        cudaFuncAttributeMaxDynamicSharedMemorySize, SCAN_SMEM_BYTES);
    cudaFuncSetAttribute(xg_gemm_mma,
        cudaFuncAttributeMaxDynamicSharedMemorySize, GEMM_SMEM_BYTES);

    // slot 0
    prep_kernel<<<1536, 256>>>(w_hh_f, w_hh_b, w1);
    // slot 1
    {
        int total = Bn*Tn*Dn + 2*G3*Dn;
        prep_split<<<(total + 255) / 256, 256>>>(feats, w_ih_f, w_ih_b);
    }
    // slot 2
    dummy_kernel<<<1, 32>>>();
    // slot 3 (profiler lands here -> measure 3-stage GEMM)
    {
        dim3 g((2 * G3) / 128, Bn * Tn / 128);   // (12, 256)
        xg_gemm_mma<<<g, 256, GEMM_SMEM_BYTES>>>(b_ih_f, b_ih_b);
    }
    // slot 4
    scan_kernel<<<128, 256, SCAN_SMEM_BYTES>>>(b_hh_f, b_hh_b, lengths);
    // slot 5
    mlp_kernel<<<Bn * Tn / 32, 256>>>(b1, w2, b2);
    // slot 6
    final_kernel<<<Bn, 256>>>(lengths, temp, w_tens, b_tens, w_ones, b_ones, out);
}